// round 11
// baseline (speedup 1.0000x reference)
#include <cuda_runtime.h>
#include <cuda_bf16.h>
#include <cstdint>

// Problem constants
#define NWIN   1024           // 16 batches * 8 * 8 windows
#define MTOT   65536          // NWIN * 64 tokens
#define CDIM   512
#define QKVN   1536

// Scratch (device globals — no allocation allowed)
__device__ __nv_bfloat16 g_xw_hi[(size_t)MTOT * CDIM];
__device__ __nv_bfloat16 g_xw_lo[(size_t)MTOT * CDIM];
__device__ float         g_qkv  [(size_t)3 * MTOT * CDIM];   // [s][w][h][t][d]
__device__ __nv_bfloat16 g_xo_hi[(size_t)MTOT * CDIM];
__device__ __nv_bfloat16 g_xo_lo[(size_t)MTOT * CDIM];
__device__ __nv_bfloat16 g_wq_hi[(size_t)QKVN * CDIM];
__device__ __nv_bfloat16 g_wq_lo[(size_t)QKVN * CDIM];
__device__ __nv_bfloat16 g_wp_hi[(size_t)CDIM * CDIM];
__device__ __nv_bfloat16 g_wp_lo[(size_t)CDIM * CDIM];

// ---------------------------------------------------------------------------
// helpers (all plain sm_80-era PTX — valid on compute_103 base target)
// ---------------------------------------------------------------------------
__device__ __forceinline__ uint32_t smem_u32(const void* p) {
    uint32_t a;
    asm("{ .reg .u64 t; cvta.to.shared.u64 t, %1; cvt.u32.u64 %0, t; }" : "=r"(a) : "l"(p));
    return a;
}
__device__ __forceinline__ void cp16(uint32_t s, const void* g) {
    asm volatile("cp.async.cg.shared.global [%0], [%1], 16;" :: "r"(s), "l"(g));
}
__device__ __forceinline__ void ldm_x4(uint32_t* r, uint32_t addr) {
    asm volatile("ldmatrix.sync.aligned.m8n8.x4.shared.b16 {%0,%1,%2,%3}, [%4];"
                 : "=r"(r[0]), "=r"(r[1]), "=r"(r[2]), "=r"(r[3]) : "r"(addr));
}
__device__ __forceinline__ void ldm_x4_t(uint32_t* r, uint32_t addr) {
    asm volatile("ldmatrix.sync.aligned.m8n8.x4.trans.shared.b16 {%0,%1,%2,%3}, [%4];"
                 : "=r"(r[0]), "=r"(r[1]), "=r"(r[2]), "=r"(r[3]) : "r"(addr));
}
__device__ __forceinline__ void mma16816(float* c, const uint32_t* a, const uint32_t* b) {
    asm volatile(
        "mma.sync.aligned.m16n8k16.row.col.f32.bf16.bf16.f32 "
        "{%0,%1,%2,%3}, {%4,%5,%6,%7}, {%8,%9}, {%0,%1,%2,%3};"
        : "+f"(c[0]), "+f"(c[1]), "+f"(c[2]), "+f"(c[3])
        : "r"(a[0]), "r"(a[1]), "r"(a[2]), "r"(a[3]), "r"(b[0]), "r"(b[1]));
}
__device__ __forceinline__ uint32_t packbf(__nv_bfloat16 a, __nv_bfloat16 b) {
    uint32_t lo = *(uint16_t*)&a, hi = *(uint16_t*)&b;
    return lo | (hi << 16);
}

// ---------------------------------------------------------------------------
// 1) Gather + bf16 split: xw[w, t, cc] = x[b, n(i,j), c]
// ---------------------------------------------------------------------------
__global__ __launch_bounds__(256) void gather_split_kernel(const float* __restrict__ x) {
    int idx = blockIdx.x * blockDim.x + threadIdx.x;      // [0, NWIN*64*64)
    int cc64 = idx & 63;
    int t    = (idx >> 6) & 63;
    int w    = idx >> 12;
    int b  = w >> 6;
    int wh = (w >> 3) & 7;
    int ww = w & 7;
    int i = cc64 >> 3;
    int j = cc64 & 7;
    int base_c = (t & 7) * 64 + (t >> 3) * 8;
    int n = (wh * 8 + i) * 64 + (ww * 8 + j);
    const float* src = x + ((size_t)(b * 4096 + n)) * 512 + base_c;
    float4 v0 = *(const float4*)(src);
    float4 v1 = *(const float4*)(src + 4);
    float vv[8] = {v0.x, v0.y, v0.z, v0.w, v1.x, v1.y, v1.z, v1.w};
    size_t off = (size_t)w * 32768 + t * 512 + cc64;
#pragma unroll
    for (int r = 0; r < 8; r++) {
        float v = vv[r];
        __nv_bfloat16 h = __float2bfloat16(v);
        g_xw_hi[off + 64 * r] = h;
        g_xw_lo[off + 64 * r] = __float2bfloat16(v - __bfloat162float(h));
    }
}

// ---------------------------------------------------------------------------
// 1b) Weight split (w_qkv 1536x512, w_proj 512x512)
// ---------------------------------------------------------------------------
__global__ __launch_bounds__(256) void wsplit_kernel(const float* __restrict__ wq,
                                                     const float* __restrict__ wp) {
    int i = blockIdx.x * blockDim.x + threadIdx.x;
    if (i < QKVN * CDIM) {
        float v = wq[i];
        __nv_bfloat16 h = __float2bfloat16(v);
        g_wq_hi[i] = h;
        g_wq_lo[i] = __float2bfloat16(v - __bfloat162float(h));
    } else {
        int k = i - QKVN * CDIM;
        float v = wp[k];
        __nv_bfloat16 h = __float2bfloat16(v);
        g_wp_hi[k] = h;
        g_wp_lo[k] = __float2bfloat16(v - __bfloat162float(h));
    }
}

// ---------------------------------------------------------------------------
// 2) Fused bf16x3 HMMA GEMM v2: per k-chunk, stage holds Ahi|Alo|Bhi|Blo and
//    all three products (Ahi*Bhi + Alo*Bhi + Ahi*Blo) are issued from it.
//    A hi/lo each stream from DRAM exactly ONCE per n-tile (was hi x2).
//    CTA tile 128x256 (BN doubled -> half the n-tiles), warp tile 64x64,
//    8 warps, 2-stage cp.async pipeline (96KB/stage), K-chunk 64.
//    mode 0: A=g_xw, B=g_wq, epilogue scatter to g_qkv[s][w][h][t][d]
//    mode 1: A=g_xo, B=g_wp, epilogue bias + window-merge to out
// ---------------------------------------------------------------------------
#define STG2   98304                 // Ahi 16K | Alo 16K | Bhi 32K | Blo 32K
#define GSMEM2 (2 * STG2 + 1024)
#define KCHUNKS 8

extern "C" __global__ __launch_bounds__(256, 1)
void gemm3_kernel(const float* __restrict__ bias, float* __restrict__ outp, int mode) {
    extern __shared__ char smem[];
    const int tid  = threadIdx.x;
    const int lane = tid & 31;
    const int wid  = tid >> 5;
    const int wm   = wid & 1;            // 2 warp rows (64 m each)
    const int wn   = wid >> 1;           // 4 warp cols (64 n each)
    const int m0 = blockIdx.x * 128;
    const int n0 = blockIdx.y * 256;

    const __nv_bfloat16* Ahi = (mode == 0) ? g_xw_hi : g_xo_hi;
    const __nv_bfloat16* Alo = (mode == 0) ? g_xw_lo : g_xo_lo;
    const __nv_bfloat16* Bhi = (mode == 0) ? g_wq_hi : g_wp_hi;
    const __nv_bfloat16* Blo = (mode == 0) ? g_wq_lo : g_wp_lo;

    uint32_t sbase = smem_u32(smem);
    uint32_t tile0 = (sbase + 1023) & ~1023u;

    float acc[4][8][4];
#pragma unroll
    for (int a = 0; a < 4; a++)
#pragma unroll
        for (int b = 0; b < 8; b++)
#pragma unroll
            for (int c = 0; c < 4; c++) acc[a][b][c] = 0.f;

    // ---- stage loader: one K-chunk (64) of Ahi,Alo(128 rows), Bhi,Blo(256 rows)
    auto load_stage = [&](int st, int kc) {
        int kb = kc << 6;
        uint32_t sg = tile0 + st * STG2;
#pragma unroll
        for (int v = 0; v < 4; v++) {                     // A hi + lo
            int c = tid + v * 256;                        // 0..1023
            int r = c >> 3, g = c & 7;
            uint32_t so = r * 128 + ((g ^ (r & 7)) << 4);
            cp16(sg + so,         Ahi + (size_t)(m0 + r) * 512 + kb + g * 8);
            cp16(sg + 16384 + so, Alo + (size_t)(m0 + r) * 512 + kb + g * 8);
        }
#pragma unroll
        for (int v = 0; v < 8; v++) {                     // B hi + lo
            int c = tid + v * 256;                        // 0..2047
            int r = c >> 3, g = c & 7;
            uint32_t so = r * 128 + ((g ^ (r & 7)) << 4);
            cp16(sg + 32768 + so, Bhi + (size_t)(n0 + r) * 512 + kb + g * 8);
            cp16(sg + 65536 + so, Blo + (size_t)(n0 + r) * 512 + kb + g * 8);
        }
        asm volatile("cp.async.commit_group;" ::: "memory");
    };

    load_stage(0, 0);
    load_stage(1, 1);

    const int la = lane & 15;
    const int hi = lane >> 4;

    for (int it = 0; it < KCHUNKS; ++it) {
        asm volatile("cp.async.wait_group 1;" ::: "memory");
        __syncthreads();

        uint32_t sg = tile0 + (it & 1) * STG2;
#pragma unroll
        for (int s = 0; s < 4; s++) {                 // 4 x k16 in the chunk
            int ch = 2 * s + hi;
            uint32_t afh[4][4], afl[4][4];
#pragma unroll
            for (int mt = 0; mt < 4; mt++) {
                int r = wm * 64 + mt * 16 + la;
                uint32_t off = r * 128 + ((ch ^ (r & 7)) << 4);
                ldm_x4(afh[mt], sg + off);
                ldm_x4(afl[mt], sg + 16384 + off);
            }
#pragma unroll
            for (int nh = 0; nh < 4; nh++) {          // 16 output cols each
                int r = wn * 64 + nh * 16 + la;
                uint32_t off = r * 128 + ((ch ^ (r & 7)) << 4);
                uint32_t th[4], tl[4];
                ldm_x4(th, sg + 32768 + off);
                ldm_x4(tl, sg + 65536 + off);
                uint32_t bh0[2] = {th[0], th[2]}, bh1[2] = {th[1], th[3]};
                uint32_t bl0[2] = {tl[0], tl[2]}, bl1[2] = {tl[1], tl[3]};
#pragma unroll
                for (int mt = 0; mt < 4; mt++) {
                    mma16816(acc[mt][nh * 2 + 0], afh[mt], bh0);   // hi*hi
                    mma16816(acc[mt][nh * 2 + 1], afh[mt], bh1);
                    mma16816(acc[mt][nh * 2 + 0], afl[mt], bh0);   // lo*hi
                    mma16816(acc[mt][nh * 2 + 1], afl[mt], bh1);
                    mma16816(acc[mt][nh * 2 + 0], afh[mt], bl0);   // hi*lo
                    mma16816(acc[mt][nh * 2 + 1], afh[mt], bl1);
                }
            }
        }
        __syncthreads();
        if (it + 2 < KCHUNKS) load_stage(it & 1, it + 2);
        else asm volatile("cp.async.commit_group;" ::: "memory");
    }

    // ---- epilogue straight from C fragments ----
    const int row0 = lane >> 2;
    const int col0 = (lane & 3) * 2;
#pragma unroll
    for (int mt = 0; mt < 4; mt++) {
#pragma unroll
        for (int half = 0; half < 2; half++) {
            int m = m0 + wm * 64 + mt * 16 + row0 + half * 8;
            int w = m >> 6, tt = m & 63;
#pragma unroll
            for (int nt = 0; nt < 8; nt++) {
                int n = n0 + wn * 64 + nt * 8 + col0;
                float v0 = acc[mt][nt][half * 2 + 0];
                float v1 = acc[mt][nt][half * 2 + 1];
                if (mode == 0) {
                    int s = n >> 9, h = (n >> 5) & 15, d = n & 31;
                    float* dst = g_qkv + (((size_t)s * NWIN + w) * 16 + h) * 2048
                               + (size_t)tt * 32 + d;
                    *(float2*)dst = make_float2(v0, v1);
                } else {
                    int b  = w >> 6;
                    int wh = (w >> 3) & 7;
                    int ww = w & 7;
                    int p = tt >> 3, q = tt & 7;
                    int npos = (wh * 8 + p) * 64 + (ww * 8 + q);
                    float2 bi = *(const float2*)(bias + n);
                    float* dst = outp + ((size_t)(b * 4096 + npos)) * 512 + n;
                    *(float2*)dst = make_float2(v0 + bi.x, v1 + bi.y);
                }
            }
        }
    }
}

// ---------------------------------------------------------------------------
// 3) Attention (HMMA, unchanged from R10): one CTA per (window, head).
// ---------------------------------------------------------------------------
#define KVSTRIDE 40   // bf16 elems per row (80B) -> conflict-free ldmatrix

__global__ __launch_bounds__(128) void attn_kernel() {
    __shared__ __nv_bfloat16 Khi[64 * KVSTRIDE], Klo[64 * KVSTRIDE];
    __shared__ __nv_bfloat16 Vhi[64 * KVSTRIDE], Vlo[64 * KVSTRIDE];
    const int tid = threadIdx.x;
    const int w = blockIdx.x >> 4;
    const int h = blockIdx.x & 15;
    const size_t base = ((size_t)w * 16 + h) * 2048;
    const float* qb = g_qkv + base;
    const float* kb = g_qkv + (size_t)MTOT * 512 + base;
    const float* vb = g_qkv + (size_t)2 * MTOT * 512 + base;

#pragma unroll
    for (int v = 0; v < 4; v++) {
        int fi = tid + v * 128;
        int row = fi >> 3, d0 = (fi & 7) * 4;
        float4 kv = *(const float4*)(kb + row * 32 + d0);
        float4 vv = *(const float4*)(vb + row * 32 + d0);
        __nv_bfloat16 kh0 = __float2bfloat16(kv.x), kh1 = __float2bfloat16(kv.y);
        __nv_bfloat16 kh2 = __float2bfloat16(kv.z), kh3 = __float2bfloat16(kv.w);
        __nv_bfloat16 vh0 = __float2bfloat16(vv.x), vh1 = __float2bfloat16(vv.y);
        __nv_bfloat16 vh2 = __float2bfloat16(vv.z), vh3 = __float2bfloat16(vv.w);
        int so = row * KVSTRIDE + d0;
        *(uint2*)(Khi + so) = make_uint2(packbf(kh0, kh1), packbf(kh2, kh3));
        *(uint2*)(Vhi + so) = make_uint2(packbf(vh0, vh1), packbf(vh2, vh3));
        *(uint2*)(Klo + so) = make_uint2(
            packbf(__float2bfloat16(kv.x - __bfloat162float(kh0)),
                   __float2bfloat16(kv.y - __bfloat162float(kh1))),
            packbf(__float2bfloat16(kv.z - __bfloat162float(kh2)),
                   __float2bfloat16(kv.w - __bfloat162float(kh3))));
        *(uint2*)(Vlo + so) = make_uint2(
            packbf(__float2bfloat16(vv.x - __bfloat162float(vh0)),
                   __float2bfloat16(vv.y - __bfloat162float(vh1))),
            packbf(__float2bfloat16(vv.z - __bfloat162float(vh2)),
                   __float2bfloat16(vv.w - __bfloat162float(vh3))));
    }
    __syncthreads();

    const int lane = tid & 31, wq = tid >> 5;
    const int g  = lane >> 2;
    const int t2 = (lane & 3) * 2;
    const uint32_t aKhi = smem_u32(Khi), aKlo = smem_u32(Klo);
    const uint32_t aVhi = smem_u32(Vhi), aVlo = smem_u32(Vlo);

    uint32_t qhi[8], qlo[8];
#pragma unroll
    for (int kt = 0; kt < 2; kt++)
#pragma unroll
        for (int pos = 0; pos < 4; pos++) {
            int row = wq * 16 + g + (pos & 1) * 8;
            int col = kt * 16 + t2 + (pos >> 1) * 8;
            float2 qv = *(const float2*)(qb + row * 32 + col);
            __nv_bfloat16 h0 = __float2bfloat16(qv.x), h1 = __float2bfloat16(qv.y);
            qhi[kt * 4 + pos] = packbf(h0, h1);
            qlo[kt * 4 + pos] = packbf(__float2bfloat16(qv.x - __bfloat162float(h0)),
                                       __float2bfloat16(qv.y - __bfloat162float(h1)));
        }

    float sc[8][4];
#pragma unroll
    for (int j = 0; j < 8; j++)
#pragma unroll
        for (int i = 0; i < 4; i++) sc[j][i] = 0.f;

#pragma unroll
    for (int pass = 0; pass < 3; pass++) {
        uint32_t kbase = (pass == 2) ? aKlo : aKhi;
        const uint32_t* qa = (pass == 1) ? qlo : qhi;
#pragma unroll
        for (int kt = 0; kt < 2; kt++) {
#pragma unroll
            for (int nb = 0; nb < 4; nb++) {
                uint32_t t4[4];
                ldm_x4(t4, kbase + (nb * 16 + (lane & 15)) * (KVSTRIDE * 2)
                             + (kt * 2 + (lane >> 4)) * 16);
                uint32_t b0[2] = {t4[0], t4[2]}, b1[2] = {t4[1], t4[3]};
                mma16816(sc[nb * 2 + 0], qa + kt * 4, b0);
                mma16816(sc[nb * 2 + 1], qa + kt * 4, b1);
            }
        }
    }

    const float scale = 0.17677669529663687f;
    float m0 = -1e30f, m1 = -1e30f;
#pragma unroll
    for (int j = 0; j < 8; j++) {
#pragma unroll
        for (int i = 0; i < 4; i++) sc[j][i] *= scale;
        m0 = fmaxf(m0, fmaxf(sc[j][0], sc[j][1]));
        m1 = fmaxf(m1, fmaxf(sc[j][2], sc[j][3]));
    }
#pragma unroll
    for (int o = 1; o < 4; o <<= 1) {
        m0 = fmaxf(m0, __shfl_xor_sync(0xffffffffu, m0, o));
        m1 = fmaxf(m1, __shfl_xor_sync(0xffffffffu, m1, o));
    }
    float s0 = 0.f, s1 = 0.f;
#pragma unroll
    for (int j = 0; j < 8; j++) {
        sc[j][0] = __expf(sc[j][0] - m0);
        sc[j][1] = __expf(sc[j][1] - m0);
        sc[j][2] = __expf(sc[j][2] - m1);
        sc[j][3] = __expf(sc[j][3] - m1);
        s0 += sc[j][0] + sc[j][1];
        s1 += sc[j][2] + sc[j][3];
    }
#pragma unroll
    for (int o = 1; o < 4; o <<= 1) {
        s0 += __shfl_xor_sync(0xffffffffu, s0, o);
        s1 += __shfl_xor_sync(0xffffffffu, s1, o);
    }

    uint32_t phi[16], plo[16];
#pragma unroll
    for (int kt = 0; kt < 4; kt++) {
#pragma unroll
        for (int pos = 0; pos < 4; pos++) {
            int j = 2 * kt + (pos >> 1);
            float a = sc[j][(pos & 1) * 2 + 0];
            float b = sc[j][(pos & 1) * 2 + 1];
            __nv_bfloat16 h0 = __float2bfloat16(a), h1 = __float2bfloat16(b);
            phi[kt * 4 + pos] = packbf(h0, h1);
            plo[kt * 4 + pos] = packbf(__float2bfloat16(a - __bfloat162float(h0)),
                                       __float2bfloat16(b - __bfloat162float(h1)));
        }
    }

    float oc[4][4];
#pragma unroll
    for (int nb = 0; nb < 4; nb++)
#pragma unroll
        for (int i = 0; i < 4; i++) oc[nb][i] = 0.f;

#pragma unroll
    for (int pass = 0; pass < 3; pass++) {
        uint32_t vbase = (pass == 1) ? aVlo : aVhi;
        const uint32_t* pa = (pass == 2) ? plo : phi;
#pragma unroll
        for (int kt = 0; kt < 4; kt++) {
#pragma unroll
            for (int dh = 0; dh < 2; dh++) {
                uint32_t t4[4];
                ldm_x4_t(t4, vbase
                    + (kt * 16 + ((lane >> 3) & 1) * 8 + (lane & 7)) * (KVSTRIDE * 2)
                    + (dh * 16 + ((lane >> 4) & 1) * 8) * 2);
                uint32_t b0[2] = {t4[0], t4[1]}, b1[2] = {t4[2], t4[3]};
                mma16816(oc[dh * 2 + 0], pa + kt * 4, b0);
                mma16816(oc[dh * 2 + 1], pa + kt * 4, b1);
            }
        }
    }

    const float i0 = 1.f / s0, i1 = 1.f / s1;
#pragma unroll
    for (int nb = 0; nb < 4; nb++) {
#pragma unroll
        for (int half = 0; half < 2; half++) {
            int row = w * 64 + wq * 16 + g + half * 8;
            int col = h * 32 + nb * 8 + t2;
            float inv = half ? i1 : i0;
            float a = oc[nb][half * 2 + 0] * inv;
            float b = oc[nb][half * 2 + 1] * inv;
            __nv_bfloat16 h0 = __float2bfloat16(a), h1 = __float2bfloat16(b);
            *(uint32_t*)(g_xo_hi + (size_t)row * 512 + col) = packbf(h0, h1);
            *(uint32_t*)(g_xo_lo + (size_t)row * 512 + col) =
                packbf(__float2bfloat16(a - __bfloat162float(h0)),
                       __float2bfloat16(b - __bfloat162float(h1)));
        }
    }
}

// ---------------------------------------------------------------------------
extern "C" void kernel_launch(void* const* d_in, const int* in_sizes, int n_in,
                              void* d_out, int out_size) {
    const float* x      = (const float*)d_in[0];
    const float* w_qkv  = (const float*)d_in[1];
    const float* w_proj = (const float*)d_in[2];
    const float* b_proj = (const float*)d_in[3];
    float* out = (float*)d_out;

    cudaFuncSetAttribute(gemm3_kernel, cudaFuncAttributeMaxDynamicSharedMemorySize, GSMEM2);

    gather_split_kernel<<<16384, 256>>>(x);
    wsplit_kernel<<<4096, 256>>>(w_qkv, w_proj);
    gemm3_kernel<<<dim3(512, 6), 256, GSMEM2>>>(nullptr, nullptr, 0);  // QKV
    attn_kernel<<<16384, 128>>>();                                     // HMMA attention
    gemm3_kernel<<<dim3(512, 2), 256, GSMEM2>>>(b_proj, out, 1);       // proj
}

// round 12
// speedup vs baseline: 1.3798x; 1.3798x over previous
#include <cuda_runtime.h>
#include <cuda_fp16.h>
#include <cuda_bf16.h>
#include <cstdint>

// Problem constants
#define NWIN   1024           // 16 batches * 8 * 8 windows
#define MTOT   65536          // NWIN * 64 tokens
#define CDIM   512
#define QKVN   1536

// Scratch (device globals — no allocation allowed)
__device__ __half        g_xw  [(size_t)MTOT * CDIM];        // A for QKV GEMM (fp16)
__device__ float         g_qkv [(size_t)3 * MTOT * CDIM];    // [s][w][h][t][d]
__device__ __half        g_xo  [(size_t)MTOT * CDIM];        // A for proj GEMM (fp16)
__device__ __half        g_wq_hi[(size_t)QKVN * CDIM];
__device__ __half        g_wq_lo[(size_t)QKVN * CDIM];
__device__ __half        g_wp_hi[(size_t)CDIM * CDIM];
__device__ __half        g_wp_lo[(size_t)CDIM * CDIM];

// ---------------------------------------------------------------------------
// helpers (all plain sm_80-era PTX — valid on compute_103 base target)
// ---------------------------------------------------------------------------
__device__ __forceinline__ uint32_t smem_u32(const void* p) {
    uint32_t a;
    asm("{ .reg .u64 t; cvta.to.shared.u64 t, %1; cvt.u32.u64 %0, t; }" : "=r"(a) : "l"(p));
    return a;
}
__device__ __forceinline__ void cp16(uint32_t s, const void* g) {
    asm volatile("cp.async.cg.shared.global [%0], [%1], 16;" :: "r"(s), "l"(g));
}
__device__ __forceinline__ void ldm_x4(uint32_t* r, uint32_t addr) {
    asm volatile("ldmatrix.sync.aligned.m8n8.x4.shared.b16 {%0,%1,%2,%3}, [%4];"
                 : "=r"(r[0]), "=r"(r[1]), "=r"(r[2]), "=r"(r[3]) : "r"(addr));
}
__device__ __forceinline__ void ldm_x4_t(uint32_t* r, uint32_t addr) {
    asm volatile("ldmatrix.sync.aligned.m8n8.x4.trans.shared.b16 {%0,%1,%2,%3}, [%4];"
                 : "=r"(r[0]), "=r"(r[1]), "=r"(r[2]), "=r"(r[3]) : "r"(addr));
}
// bf16 mma (attention)
__device__ __forceinline__ void mma16816(float* c, const uint32_t* a, const uint32_t* b) {
    asm volatile(
        "mma.sync.aligned.m16n8k16.row.col.f32.bf16.bf16.f32 "
        "{%0,%1,%2,%3}, {%4,%5,%6,%7}, {%8,%9}, {%0,%1,%2,%3};"
        : "+f"(c[0]), "+f"(c[1]), "+f"(c[2]), "+f"(c[3])
        : "r"(a[0]), "r"(a[1]), "r"(a[2]), "r"(a[3]), "r"(b[0]), "r"(b[1]));
}
// fp16 mma (GEMMs)
__device__ __forceinline__ void mma16816h(float* c, const uint32_t* a, const uint32_t* b) {
    asm volatile(
        "mma.sync.aligned.m16n8k16.row.col.f32.f16.f16.f32 "
        "{%0,%1,%2,%3}, {%4,%5,%6,%7}, {%8,%9}, {%0,%1,%2,%3};"
        : "+f"(c[0]), "+f"(c[1]), "+f"(c[2]), "+f"(c[3])
        : "r"(a[0]), "r"(a[1]), "r"(a[2]), "r"(a[3]), "r"(b[0]), "r"(b[1]));
}
__device__ __forceinline__ uint32_t packbf(__nv_bfloat16 a, __nv_bfloat16 b) {
    uint32_t lo = *(uint16_t*)&a, hi = *(uint16_t*)&b;
    return lo | (hi << 16);
}
__device__ __forceinline__ uint32_t packh(float a, float b) {
    __half ha = __float2half(a), hb = __float2half(b);
    uint32_t lo = *(uint16_t*)&ha, hi = *(uint16_t*)&hb;
    return lo | (hi << 16);
}

// ---------------------------------------------------------------------------
// 1) Gather + fp16 round: xw[w, t, cc] = fp16(x[b, n(i,j), c])
// ---------------------------------------------------------------------------
__global__ __launch_bounds__(256) void gather_kernel(const float* __restrict__ x) {
    int idx = blockIdx.x * blockDim.x + threadIdx.x;      // [0, NWIN*64*64)
    int cc64 = idx & 63;
    int t    = (idx >> 6) & 63;
    int w    = idx >> 12;
    int b  = w >> 6;
    int wh = (w >> 3) & 7;
    int ww = w & 7;
    int i = cc64 >> 3;
    int j = cc64 & 7;
    int base_c = (t & 7) * 64 + (t >> 3) * 8;
    int n = (wh * 8 + i) * 64 + (ww * 8 + j);
    const float* src = x + ((size_t)(b * 4096 + n)) * 512 + base_c;
    float4 v0 = *(const float4*)(src);
    float4 v1 = *(const float4*)(src + 4);
    float vv[8] = {v0.x, v0.y, v0.z, v0.w, v1.x, v1.y, v1.z, v1.w};
    size_t off = (size_t)w * 32768 + t * 512 + cc64;
#pragma unroll
    for (int r = 0; r < 8; r++) g_xw[off + 64 * r] = __float2half(vv[r]);
}

// ---------------------------------------------------------------------------
// 1b) Weight split into exact fp16 hi/lo pairs
// ---------------------------------------------------------------------------
__global__ __launch_bounds__(256) void wsplit_kernel(const float* __restrict__ wq,
                                                     const float* __restrict__ wp) {
    int i = blockIdx.x * blockDim.x + threadIdx.x;
    if (i < QKVN * CDIM) {
        float v = wq[i];
        __half h = __float2half(v);
        g_wq_hi[i] = h;
        g_wq_lo[i] = __float2half(v - __half2float(h));
    } else {
        int k = i - QKVN * CDIM;
        float v = wp[k];
        __half h = __float2half(v);
        g_wp_hi[k] = h;
        g_wp_lo[k] = __float2half(v - __half2float(h));
    }
}

// ---------------------------------------------------------------------------
// 2) fp16x2 HMMA GEMM: D = A16 * (Bhi + Blo), 2 MMA passes fused per k-chunk.
//    A rounded to fp16 (err 2^-11, dot-product rel err ~3e-4); B exact hi+lo.
//    CTA tile 128x256, warp tile 64x64, 8 warps, 2-stage cp.async pipeline,
//    K-chunk 64 (128B rows, XOR-16B swizzle, conflict-free ldmatrix).
//    mode 0: A=g_xw, B=g_wq, epilogue scatter to g_qkv[s][w][h][t][d]
//    mode 1: A=g_xo, B=g_wp, epilogue bias + window-merge to out
// ---------------------------------------------------------------------------
#define STG3   81920                 // A 16K | Bhi 32K | Blo 32K
#define GSMEM3 (2 * STG3 + 1024)
#define KCHUNKS 8

extern "C" __global__ __launch_bounds__(256, 1)
void gemm2_kernel(const float* __restrict__ bias, float* __restrict__ outp, int mode) {
    extern __shared__ char smem[];
    const int tid  = threadIdx.x;
    const int lane = tid & 31;
    const int wid  = tid >> 5;
    const int wm   = wid & 1;            // 2 warp rows (64 m each)
    const int wn   = wid >> 1;           // 4 warp cols (64 n each)
    const int m0 = blockIdx.x * 128;
    const int n0 = blockIdx.y * 256;

    const __half* A16 = (mode == 0) ? g_xw : g_xo;
    const __half* Bhi = (mode == 0) ? g_wq_hi : g_wp_hi;
    const __half* Blo = (mode == 0) ? g_wq_lo : g_wp_lo;

    uint32_t sbase = smem_u32(smem);
    uint32_t tile0 = (sbase + 1023) & ~1023u;

    float acc[4][8][4];
#pragma unroll
    for (int a = 0; a < 4; a++)
#pragma unroll
        for (int b = 0; b < 8; b++)
#pragma unroll
            for (int c = 0; c < 4; c++) acc[a][b][c] = 0.f;

    // ---- stage loader: one K-chunk (64) of A(128 rows), Bhi,Blo(256 rows) ----
    auto load_stage = [&](int st, int kc) {
        int kb = kc << 6;
        uint32_t sg = tile0 + st * STG3;
#pragma unroll
        for (int v = 0; v < 4; v++) {                     // A: 1024 x 16B
            int c = tid + v * 256;
            int r = c >> 3, g = c & 7;
            uint32_t so = r * 128 + ((g ^ (r & 7)) << 4);
            cp16(sg + so, A16 + (size_t)(m0 + r) * 512 + kb + g * 8);
        }
#pragma unroll
        for (int v = 0; v < 8; v++) {                     // B hi+lo: 2048 x 16B each
            int c = tid + v * 256;
            int r = c >> 3, g = c & 7;
            uint32_t so = r * 128 + ((g ^ (r & 7)) << 4);
            cp16(sg + 16384 + so, Bhi + (size_t)(n0 + r) * 512 + kb + g * 8);
            cp16(sg + 49152 + so, Blo + (size_t)(n0 + r) * 512 + kb + g * 8);
        }
        asm volatile("cp.async.commit_group;" ::: "memory");
    };

    load_stage(0, 0);
    load_stage(1, 1);

    const int la = lane & 15;
    const int hi = lane >> 4;

    for (int it = 0; it < KCHUNKS; ++it) {
        asm volatile("cp.async.wait_group 1;" ::: "memory");
        __syncthreads();

        uint32_t sg = tile0 + (it & 1) * STG3;
#pragma unroll
        for (int s = 0; s < 4; s++) {                 // 4 x k16 in the chunk
            int ch = 2 * s + hi;
            uint32_t af[4][4];
#pragma unroll
            for (int mt = 0; mt < 4; mt++) {
                int r = wm * 64 + mt * 16 + la;
                ldm_x4(af[mt], sg + r * 128 + ((ch ^ (r & 7)) << 4));
            }
#pragma unroll
            for (int nh = 0; nh < 4; nh++) {          // 16 output cols each
                int r = wn * 64 + nh * 16 + la;
                uint32_t off = r * 128 + ((ch ^ (r & 7)) << 4);
                uint32_t th[4], tl[4];
                ldm_x4(th, sg + 16384 + off);
                ldm_x4(tl, sg + 49152 + off);
                uint32_t bh0[2] = {th[0], th[2]}, bh1[2] = {th[1], th[3]};
                uint32_t bl0[2] = {tl[0], tl[2]}, bl1[2] = {tl[1], tl[3]};
#pragma unroll
                for (int mt = 0; mt < 4; mt++) {
                    mma16816h(acc[mt][nh * 2 + 0], af[mt], bh0);   // A*Bhi
                    mma16816h(acc[mt][nh * 2 + 1], af[mt], bh1);
                    mma16816h(acc[mt][nh * 2 + 0], af[mt], bl0);   // A*Blo
                    mma16816h(acc[mt][nh * 2 + 1], af[mt], bl1);
                }
            }
        }
        __syncthreads();
        if (it + 2 < KCHUNKS) load_stage(it & 1, it + 2);
        else asm volatile("cp.async.commit_group;" ::: "memory");
    }

    // ---- epilogue straight from C fragments ----
    const int row0 = lane >> 2;
    const int col0 = (lane & 3) * 2;
#pragma unroll
    for (int mt = 0; mt < 4; mt++) {
#pragma unroll
        for (int half = 0; half < 2; half++) {
            int m = m0 + wm * 64 + mt * 16 + row0 + half * 8;
            int w = m >> 6, tt = m & 63;
#pragma unroll
            for (int nt = 0; nt < 8; nt++) {
                int n = n0 + wn * 64 + nt * 8 + col0;
                float v0 = acc[mt][nt][half * 2 + 0];
                float v1 = acc[mt][nt][half * 2 + 1];
                if (mode == 0) {
                    int s = n >> 9, h = (n >> 5) & 15, d = n & 31;
                    float* dst = g_qkv + (((size_t)s * NWIN + w) * 16 + h) * 2048
                               + (size_t)tt * 32 + d;
                    *(float2*)dst = make_float2(v0, v1);
                } else {
                    int b  = w >> 6;
                    int wh = (w >> 3) & 7;
                    int ww = w & 7;
                    int p = tt >> 3, q = tt & 7;
                    int npos = (wh * 8 + p) * 64 + (ww * 8 + q);
                    float2 bi = *(const float2*)(bias + n);
                    float* dst = outp + ((size_t)(b * 4096 + npos)) * 512 + n;
                    *(float2*)dst = make_float2(v0 + bi.x, v1 + bi.y);
                }
            }
        }
    }
}

// ---------------------------------------------------------------------------
// 3) Attention (HMMA bf16x3, unchanged math): one CTA per (window, head).
//    Epilogue now emits single fp16 xo for the proj GEMM.
// ---------------------------------------------------------------------------
#define KVSTRIDE 40   // bf16 elems per row (80B) -> conflict-free ldmatrix

__global__ __launch_bounds__(128) void attn_kernel() {
    __shared__ __nv_bfloat16 Khi[64 * KVSTRIDE], Klo[64 * KVSTRIDE];
    __shared__ __nv_bfloat16 Vhi[64 * KVSTRIDE], Vlo[64 * KVSTRIDE];
    const int tid = threadIdx.x;
    const int w = blockIdx.x >> 4;
    const int h = blockIdx.x & 15;
    const size_t base = ((size_t)w * 16 + h) * 2048;
    const float* qb = g_qkv + base;
    const float* kb = g_qkv + (size_t)MTOT * 512 + base;
    const float* vb = g_qkv + (size_t)2 * MTOT * 512 + base;

#pragma unroll
    for (int v = 0; v < 4; v++) {
        int fi = tid + v * 128;
        int row = fi >> 3, d0 = (fi & 7) * 4;
        float4 kv = *(const float4*)(kb + row * 32 + d0);
        float4 vv = *(const float4*)(vb + row * 32 + d0);
        __nv_bfloat16 kh0 = __float2bfloat16(kv.x), kh1 = __float2bfloat16(kv.y);
        __nv_bfloat16 kh2 = __float2bfloat16(kv.z), kh3 = __float2bfloat16(kv.w);
        __nv_bfloat16 vh0 = __float2bfloat16(vv.x), vh1 = __float2bfloat16(vv.y);
        __nv_bfloat16 vh2 = __float2bfloat16(vv.z), vh3 = __float2bfloat16(vv.w);
        int so = row * KVSTRIDE + d0;
        *(uint2*)(Khi + so) = make_uint2(packbf(kh0, kh1), packbf(kh2, kh3));
        *(uint2*)(Vhi + so) = make_uint2(packbf(vh0, vh1), packbf(vh2, vh3));
        *(uint2*)(Klo + so) = make_uint2(
            packbf(__float2bfloat16(kv.x - __bfloat162float(kh0)),
                   __float2bfloat16(kv.y - __bfloat162float(kh1))),
            packbf(__float2bfloat16(kv.z - __bfloat162float(kh2)),
                   __float2bfloat16(kv.w - __bfloat162float(kh3))));
        *(uint2*)(Vlo + so) = make_uint2(
            packbf(__float2bfloat16(vv.x - __bfloat162float(vh0)),
                   __float2bfloat16(vv.y - __bfloat162float(vh1))),
            packbf(__float2bfloat16(vv.z - __bfloat162float(vh2)),
                   __float2bfloat16(vv.w - __bfloat162float(vh3))));
    }
    __syncthreads();

    const int lane = tid & 31, wq = tid >> 5;
    const int g  = lane >> 2;
    const int t2 = (lane & 3) * 2;
    const uint32_t aKhi = smem_u32(Khi), aKlo = smem_u32(Klo);
    const uint32_t aVhi = smem_u32(Vhi), aVlo = smem_u32(Vlo);

    uint32_t qhi[8], qlo[8];
#pragma unroll
    for (int kt = 0; kt < 2; kt++)
#pragma unroll
        for (int pos = 0; pos < 4; pos++) {
            int row = wq * 16 + g + (pos & 1) * 8;
            int col = kt * 16 + t2 + (pos >> 1) * 8;
            float2 qv = *(const float2*)(qb + row * 32 + col);
            __nv_bfloat16 h0 = __float2bfloat16(qv.x), h1 = __float2bfloat16(qv.y);
            qhi[kt * 4 + pos] = packbf(h0, h1);
            qlo[kt * 4 + pos] = packbf(__float2bfloat16(qv.x - __bfloat162float(h0)),
                                       __float2bfloat16(qv.y - __bfloat162float(h1)));
        }

    float sc[8][4];
#pragma unroll
    for (int j = 0; j < 8; j++)
#pragma unroll
        for (int i = 0; i < 4; i++) sc[j][i] = 0.f;

#pragma unroll
    for (int pass = 0; pass < 3; pass++) {
        uint32_t kbase = (pass == 2) ? aKlo : aKhi;
        const uint32_t* qa = (pass == 1) ? qlo : qhi;
#pragma unroll
        for (int kt = 0; kt < 2; kt++) {
#pragma unroll
            for (int nb = 0; nb < 4; nb++) {
                uint32_t t4[4];
                ldm_x4(t4, kbase + (nb * 16 + (lane & 15)) * (KVSTRIDE * 2)
                             + (kt * 2 + (lane >> 4)) * 16);
                uint32_t b0[2] = {t4[0], t4[2]}, b1[2] = {t4[1], t4[3]};
                mma16816(sc[nb * 2 + 0], qa + kt * 4, b0);
                mma16816(sc[nb * 2 + 1], qa + kt * 4, b1);
            }
        }
    }

    const float scale = 0.17677669529663687f;
    float m0 = -1e30f, m1 = -1e30f;
#pragma unroll
    for (int j = 0; j < 8; j++) {
#pragma unroll
        for (int i = 0; i < 4; i++) sc[j][i] *= scale;
        m0 = fmaxf(m0, fmaxf(sc[j][0], sc[j][1]));
        m1 = fmaxf(m1, fmaxf(sc[j][2], sc[j][3]));
    }
#pragma unroll
    for (int o = 1; o < 4; o <<= 1) {
        m0 = fmaxf(m0, __shfl_xor_sync(0xffffffffu, m0, o));
        m1 = fmaxf(m1, __shfl_xor_sync(0xffffffffu, m1, o));
    }
    float s0 = 0.f, s1 = 0.f;
#pragma unroll
    for (int j = 0; j < 8; j++) {
        sc[j][0] = __expf(sc[j][0] - m0);
        sc[j][1] = __expf(sc[j][1] - m0);
        sc[j][2] = __expf(sc[j][2] - m1);
        sc[j][3] = __expf(sc[j][3] - m1);
        s0 += sc[j][0] + sc[j][1];
        s1 += sc[j][2] + sc[j][3];
    }
#pragma unroll
    for (int o = 1; o < 4; o <<= 1) {
        s0 += __shfl_xor_sync(0xffffffffu, s0, o);
        s1 += __shfl_xor_sync(0xffffffffu, s1, o);
    }

    uint32_t phi[16], plo[16];
#pragma unroll
    for (int kt = 0; kt < 4; kt++) {
#pragma unroll
        for (int pos = 0; pos < 4; pos++) {
            int j = 2 * kt + (pos >> 1);
            float a = sc[j][(pos & 1) * 2 + 0];
            float b = sc[j][(pos & 1) * 2 + 1];
            __nv_bfloat16 h0 = __float2bfloat16(a), h1 = __float2bfloat16(b);
            phi[kt * 4 + pos] = packbf(h0, h1);
            plo[kt * 4 + pos] = packbf(__float2bfloat16(a - __bfloat162float(h0)),
                                       __float2bfloat16(b - __bfloat162float(h1)));
        }
    }

    float oc[4][4];
#pragma unroll
    for (int nb = 0; nb < 4; nb++)
#pragma unroll
        for (int i = 0; i < 4; i++) oc[nb][i] = 0.f;

#pragma unroll
    for (int pass = 0; pass < 3; pass++) {
        uint32_t vbase = (pass == 1) ? aVlo : aVhi;
        const uint32_t* pa = (pass == 2) ? plo : phi;
#pragma unroll
        for (int kt = 0; kt < 4; kt++) {
#pragma unroll
            for (int dh = 0; dh < 2; dh++) {
                uint32_t t4[4];
                ldm_x4_t(t4, vbase
                    + (kt * 16 + ((lane >> 3) & 1) * 8 + (lane & 7)) * (KVSTRIDE * 2)
                    + (dh * 16 + ((lane >> 4) & 1) * 8) * 2);
                uint32_t b0[2] = {t4[0], t4[1]}, b1[2] = {t4[2], t4[3]};
                mma16816(oc[dh * 2 + 0], pa + kt * 4, b0);
                mma16816(oc[dh * 2 + 1], pa + kt * 4, b1);
            }
        }
    }

    const float i0 = 1.f / s0, i1 = 1.f / s1;
#pragma unroll
    for (int nb = 0; nb < 4; nb++) {
#pragma unroll
        for (int half = 0; half < 2; half++) {
            int row = w * 64 + wq * 16 + g + half * 8;
            int col = h * 32 + nb * 8 + t2;
            float inv = half ? i1 : i0;
            float a = oc[nb][half * 2 + 0] * inv;
            float b = oc[nb][half * 2 + 1] * inv;
            *(uint32_t*)(g_xo + (size_t)row * 512 + col) = packh(a, b);
        }
    }
}

// ---------------------------------------------------------------------------
extern "C" void kernel_launch(void* const* d_in, const int* in_sizes, int n_in,
                              void* d_out, int out_size) {
    const float* x      = (const float*)d_in[0];
    const float* w_qkv  = (const float*)d_in[1];
    const float* w_proj = (const float*)d_in[2];
    const float* b_proj = (const float*)d_in[3];
    float* out = (float*)d_out;

    cudaFuncSetAttribute(gemm2_kernel, cudaFuncAttributeMaxDynamicSharedMemorySize, GSMEM3);

    gather_kernel<<<16384, 256>>>(x);
    wsplit_kernel<<<4096, 256>>>(w_qkv, w_proj);
    gemm2_kernel<<<dim3(512, 6), 256, GSMEM3>>>(nullptr, nullptr, 0);  // QKV
    attn_kernel<<<16384, 128>>>();                                     // HMMA attention
    gemm2_kernel<<<dim3(512, 2), 256, GSMEM3>>>(b_proj, out, 1);       // proj
}

// round 13
// speedup vs baseline: 2.0388x; 1.4776x over previous
#include <cuda_runtime.h>
#include <cuda_fp16.h>
#include <cuda_bf16.h>
#include <cstdint>

// Problem constants
#define NWIN   1024           // 16 batches * 8 * 8 windows
#define MTOT   65536          // NWIN * 64 tokens
#define CDIM   512
#define QKVN   1536

// Scratch (device globals — no allocation allowed)
__device__ __half        g_xw  [(size_t)MTOT * CDIM];        // A for QKV GEMM (fp16)
__device__ float         g_qkv [(size_t)3 * MTOT * CDIM];    // [s][w][h][t][d]
__device__ __half        g_xo  [(size_t)MTOT * CDIM];        // A for proj GEMM (fp16)
__device__ __half        g_wq  [(size_t)QKVN * CDIM];        // fp16 weights
__device__ __half        g_wp  [(size_t)CDIM * CDIM];

// ---------------------------------------------------------------------------
// helpers (all plain sm_80-era PTX — valid on compute_103 base target)
// ---------------------------------------------------------------------------
__device__ __forceinline__ uint32_t smem_u32(const void* p) {
    uint32_t a;
    asm("{ .reg .u64 t; cvta.to.shared.u64 t, %1; cvt.u32.u64 %0, t; }" : "=r"(a) : "l"(p));
    return a;
}
__device__ __forceinline__ void cp16(uint32_t s, const void* g) {
    asm volatile("cp.async.cg.shared.global [%0], [%1], 16;" :: "r"(s), "l"(g));
}
__device__ __forceinline__ void ldm_x4(uint32_t* r, uint32_t addr) {
    asm volatile("ldmatrix.sync.aligned.m8n8.x4.shared.b16 {%0,%1,%2,%3}, [%4];"
                 : "=r"(r[0]), "=r"(r[1]), "=r"(r[2]), "=r"(r[3]) : "r"(addr));
}
__device__ __forceinline__ void ldm_x4_t(uint32_t* r, uint32_t addr) {
    asm volatile("ldmatrix.sync.aligned.m8n8.x4.trans.shared.b16 {%0,%1,%2,%3}, [%4];"
                 : "=r"(r[0]), "=r"(r[1]), "=r"(r[2]), "=r"(r[3]) : "r"(addr));
}
// bf16 mma (attention)
__device__ __forceinline__ void mma16816(float* c, const uint32_t* a, const uint32_t* b) {
    asm volatile(
        "mma.sync.aligned.m16n8k16.row.col.f32.bf16.bf16.f32 "
        "{%0,%1,%2,%3}, {%4,%5,%6,%7}, {%8,%9}, {%0,%1,%2,%3};"
        : "+f"(c[0]), "+f"(c[1]), "+f"(c[2]), "+f"(c[3])
        : "r"(a[0]), "r"(a[1]), "r"(a[2]), "r"(a[3]), "r"(b[0]), "r"(b[1]));
}
// fp16 mma (GEMMs)
__device__ __forceinline__ void mma16816h(float* c, const uint32_t* a, const uint32_t* b) {
    asm volatile(
        "mma.sync.aligned.m16n8k16.row.col.f32.f16.f16.f32 "
        "{%0,%1,%2,%3}, {%4,%5,%6,%7}, {%8,%9}, {%0,%1,%2,%3};"
        : "+f"(c[0]), "+f"(c[1]), "+f"(c[2]), "+f"(c[3])
        : "r"(a[0]), "r"(a[1]), "r"(a[2]), "r"(a[3]), "r"(b[0]), "r"(b[1]));
}
__device__ __forceinline__ uint32_t packbf(__nv_bfloat16 a, __nv_bfloat16 b) {
    uint32_t lo = *(uint16_t*)&a, hi = *(uint16_t*)&b;
    return lo | (hi << 16);
}
__device__ __forceinline__ uint32_t packh(float a, float b) {
    __half ha = __float2half(a), hb = __float2half(b);
    uint32_t lo = *(uint16_t*)&ha, hi = *(uint16_t*)&hb;
    return lo | (hi << 16);
}

// ---------------------------------------------------------------------------
// 1) Gather + fp16 round: xw[w, t, cc] = fp16(x[b, n(i,j), c])
// ---------------------------------------------------------------------------
__global__ __launch_bounds__(256) void gather_kernel(const float* __restrict__ x) {
    int idx = blockIdx.x * blockDim.x + threadIdx.x;      // [0, NWIN*64*64)
    int cc64 = idx & 63;
    int t    = (idx >> 6) & 63;
    int w    = idx >> 12;
    int b  = w >> 6;
    int wh = (w >> 3) & 7;
    int ww = w & 7;
    int i = cc64 >> 3;
    int j = cc64 & 7;
    int base_c = (t & 7) * 64 + (t >> 3) * 8;
    int n = (wh * 8 + i) * 64 + (ww * 8 + j);
    const float* src = x + ((size_t)(b * 4096 + n)) * 512 + base_c;
    float4 v0 = *(const float4*)(src);
    float4 v1 = *(const float4*)(src + 4);
    float vv[8] = {v0.x, v0.y, v0.z, v0.w, v1.x, v1.y, v1.z, v1.w};
    size_t off = (size_t)w * 32768 + t * 512 + cc64;
#pragma unroll
    for (int r = 0; r < 8; r++) g_xw[off + 64 * r] = __float2half(vv[r]);
}

// ---------------------------------------------------------------------------
// 1b) Weight convert to fp16
// ---------------------------------------------------------------------------
__global__ __launch_bounds__(256) void wsplit_kernel(const float* __restrict__ wq,
                                                     const float* __restrict__ wp) {
    int i = blockIdx.x * blockDim.x + threadIdx.x;
    if (i < QKVN * CDIM) g_wq[i] = __float2half(wq[i]);
    else                 g_wp[i - QKVN * CDIM] = __float2half(wp[i - QKVN * CDIM]);
}

// ---------------------------------------------------------------------------
// 2) fp16 single-pass HMMA GEMM: D = A16 * B16 (fp32 accum).
//    A and B both rounded to fp16 (combined dot rel err ~3-5e-4 < 1e-3 gate).
//    CTA tile 128x256, warp tile 64x64, 8 warps, 2-stage cp.async pipeline,
//    K-chunk 64 (128B rows, XOR-16B swizzle, conflict-free ldmatrix).
//    mode 0: A=g_xw, B=g_wq, epilogue scatter to g_qkv[s][w][h][t][d]
//    mode 1: A=g_xo, B=g_wp, epilogue bias + window-merge to out
// ---------------------------------------------------------------------------
#define STG4   49152                 // A 16K | B 32K
#define GSMEM4 (2 * STG4 + 1024)
#define KCHUNKS 8

extern "C" __global__ __launch_bounds__(256, 1)
void gemm1_kernel(const float* __restrict__ bias, float* __restrict__ outp, int mode) {
    extern __shared__ char smem[];
    const int tid  = threadIdx.x;
    const int lane = tid & 31;
    const int wid  = tid >> 5;
    const int wm   = wid & 1;            // 2 warp rows (64 m each)
    const int wn   = wid >> 1;           // 4 warp cols (64 n each)
    const int m0 = blockIdx.x * 128;
    const int n0 = blockIdx.y * 256;

    const __half* A16 = (mode == 0) ? g_xw : g_xo;
    const __half* B16 = (mode == 0) ? g_wq : g_wp;

    uint32_t sbase = smem_u32(smem);
    uint32_t tile0 = (sbase + 1023) & ~1023u;

    float acc[4][8][4];
#pragma unroll
    for (int a = 0; a < 4; a++)
#pragma unroll
        for (int b = 0; b < 8; b++)
#pragma unroll
            for (int c = 0; c < 4; c++) acc[a][b][c] = 0.f;

    // ---- stage loader: one K-chunk (64) of A(128 rows), B(256 rows) ----
    auto load_stage = [&](int st, int kc) {
        int kb = kc << 6;
        uint32_t sg = tile0 + st * STG4;
#pragma unroll
        for (int v = 0; v < 4; v++) {                     // A: 1024 x 16B
            int c = tid + v * 256;
            int r = c >> 3, g = c & 7;
            uint32_t so = r * 128 + ((g ^ (r & 7)) << 4);
            cp16(sg + so, A16 + (size_t)(m0 + r) * 512 + kb + g * 8);
        }
#pragma unroll
        for (int v = 0; v < 8; v++) {                     // B: 2048 x 16B
            int c = tid + v * 256;
            int r = c >> 3, g = c & 7;
            uint32_t so = r * 128 + ((g ^ (r & 7)) << 4);
            cp16(sg + 16384 + so, B16 + (size_t)(n0 + r) * 512 + kb + g * 8);
        }
        asm volatile("cp.async.commit_group;" ::: "memory");
    };

    load_stage(0, 0);
    load_stage(1, 1);

    const int la = lane & 15;
    const int hi = lane >> 4;

    for (int it = 0; it < KCHUNKS; ++it) {
        asm volatile("cp.async.wait_group 1;" ::: "memory");
        __syncthreads();

        uint32_t sg = tile0 + (it & 1) * STG4;
#pragma unroll
        for (int s = 0; s < 4; s++) {                 // 4 x k16 in the chunk
            int ch = 2 * s + hi;
            uint32_t af[4][4];
#pragma unroll
            for (int mt = 0; mt < 4; mt++) {
                int r = wm * 64 + mt * 16 + la;
                ldm_x4(af[mt], sg + r * 128 + ((ch ^ (r & 7)) << 4));
            }
#pragma unroll
            for (int nh = 0; nh < 4; nh++) {          // 16 output cols each
                int r = wn * 64 + nh * 16 + la;
                uint32_t off = r * 128 + ((ch ^ (r & 7)) << 4);
                uint32_t th[4];
                ldm_x4(th, sg + 16384 + off);
                uint32_t bh0[2] = {th[0], th[2]}, bh1[2] = {th[1], th[3]};
#pragma unroll
                for (int mt = 0; mt < 4; mt++) {
                    mma16816h(acc[mt][nh * 2 + 0], af[mt], bh0);
                    mma16816h(acc[mt][nh * 2 + 1], af[mt], bh1);
                }
            }
        }
        __syncthreads();
        if (it + 2 < KCHUNKS) load_stage(it & 1, it + 2);
        else asm volatile("cp.async.commit_group;" ::: "memory");
    }

    // ---- epilogue straight from C fragments ----
    const int row0 = lane >> 2;
    const int col0 = (lane & 3) * 2;
#pragma unroll
    for (int mt = 0; mt < 4; mt++) {
#pragma unroll
        for (int half = 0; half < 2; half++) {
            int m = m0 + wm * 64 + mt * 16 + row0 + half * 8;
            int w = m >> 6, tt = m & 63;
#pragma unroll
            for (int nt = 0; nt < 8; nt++) {
                int n = n0 + wn * 64 + nt * 8 + col0;
                float v0 = acc[mt][nt][half * 2 + 0];
                float v1 = acc[mt][nt][half * 2 + 1];
                if (mode == 0) {
                    int s = n >> 9, h = (n >> 5) & 15, d = n & 31;
                    float* dst = g_qkv + (((size_t)s * NWIN + w) * 16 + h) * 2048
                               + (size_t)tt * 32 + d;
                    *(float2*)dst = make_float2(v0, v1);
                } else {
                    int b  = w >> 6;
                    int wh = (w >> 3) & 7;
                    int ww = w & 7;
                    int p = tt >> 3, q = tt & 7;
                    int npos = (wh * 8 + p) * 64 + (ww * 8 + q);
                    float2 bi = *(const float2*)(bias + n);
                    float* dst = outp + ((size_t)(b * 4096 + npos)) * 512 + n;
                    *(float2*)dst = make_float2(v0 + bi.x, v1 + bi.y);
                }
            }
        }
    }
}

// ---------------------------------------------------------------------------
// 3) Attention (HMMA bf16x3, unchanged): one CTA per (window, head).
//    Epilogue emits single fp16 xo for the proj GEMM.
// ---------------------------------------------------------------------------
#define KVSTRIDE 40   // bf16 elems per row (80B) -> conflict-free ldmatrix

__global__ __launch_bounds__(128) void attn_kernel() {
    __shared__ __nv_bfloat16 Khi[64 * KVSTRIDE], Klo[64 * KVSTRIDE];
    __shared__ __nv_bfloat16 Vhi[64 * KVSTRIDE], Vlo[64 * KVSTRIDE];
    const int tid = threadIdx.x;
    const int w = blockIdx.x >> 4;
    const int h = blockIdx.x & 15;
    const size_t base = ((size_t)w * 16 + h) * 2048;
    const float* qb = g_qkv + base;
    const float* kb = g_qkv + (size_t)MTOT * 512 + base;
    const float* vb = g_qkv + (size_t)2 * MTOT * 512 + base;

#pragma unroll
    for (int v = 0; v < 4; v++) {
        int fi = tid + v * 128;
        int row = fi >> 3, d0 = (fi & 7) * 4;
        float4 kv = *(const float4*)(kb + row * 32 + d0);
        float4 vv = *(const float4*)(vb + row * 32 + d0);
        __nv_bfloat16 kh0 = __float2bfloat16(kv.x), kh1 = __float2bfloat16(kv.y);
        __nv_bfloat16 kh2 = __float2bfloat16(kv.z), kh3 = __float2bfloat16(kv.w);
        __nv_bfloat16 vh0 = __float2bfloat16(vv.x), vh1 = __float2bfloat16(vv.y);
        __nv_bfloat16 vh2 = __float2bfloat16(vv.z), vh3 = __float2bfloat16(vv.w);
        int so = row * KVSTRIDE + d0;
        *(uint2*)(Khi + so) = make_uint2(packbf(kh0, kh1), packbf(kh2, kh3));
        *(uint2*)(Vhi + so) = make_uint2(packbf(vh0, vh1), packbf(vh2, vh3));
        *(uint2*)(Klo + so) = make_uint2(
            packbf(__float2bfloat16(kv.x - __bfloat162float(kh0)),
                   __float2bfloat16(kv.y - __bfloat162float(kh1))),
            packbf(__float2bfloat16(kv.z - __bfloat162float(kh2)),
                   __float2bfloat16(kv.w - __bfloat162float(kh3))));
        *(uint2*)(Vlo + so) = make_uint2(
            packbf(__float2bfloat16(vv.x - __bfloat162float(vh0)),
                   __float2bfloat16(vv.y - __bfloat162float(vh1))),
            packbf(__float2bfloat16(vv.z - __bfloat162float(vh2)),
                   __float2bfloat16(vv.w - __bfloat162float(vh3))));
    }
    __syncthreads();

    const int lane = tid & 31, wq = tid >> 5;
    const int g  = lane >> 2;
    const int t2 = (lane & 3) * 2;
    const uint32_t aKhi = smem_u32(Khi), aKlo = smem_u32(Klo);
    const uint32_t aVhi = smem_u32(Vhi), aVlo = smem_u32(Vlo);

    uint32_t qhi[8], qlo[8];
#pragma unroll
    for (int kt = 0; kt < 2; kt++)
#pragma unroll
        for (int pos = 0; pos < 4; pos++) {
            int row = wq * 16 + g + (pos & 1) * 8;
            int col = kt * 16 + t2 + (pos >> 1) * 8;
            float2 qv = *(const float2*)(qb + row * 32 + col);
            __nv_bfloat16 h0 = __float2bfloat16(qv.x), h1 = __float2bfloat16(qv.y);
            qhi[kt * 4 + pos] = packbf(h0, h1);
            qlo[kt * 4 + pos] = packbf(__float2bfloat16(qv.x - __bfloat162float(h0)),
                                       __float2bfloat16(qv.y - __bfloat162float(h1)));
        }

    float sc[8][4];
#pragma unroll
    for (int j = 0; j < 8; j++)
#pragma unroll
        for (int i = 0; i < 4; i++) sc[j][i] = 0.f;

#pragma unroll
    for (int pass = 0; pass < 3; pass++) {
        uint32_t kbase = (pass == 2) ? aKlo : aKhi;
        const uint32_t* qa = (pass == 1) ? qlo : qhi;
#pragma unroll
        for (int kt = 0; kt < 2; kt++) {
#pragma unroll
            for (int nb = 0; nb < 4; nb++) {
                uint32_t t4[4];
                ldm_x4(t4, kbase + (nb * 16 + (lane & 15)) * (KVSTRIDE * 2)
                             + (kt * 2 + (lane >> 4)) * 16);
                uint32_t b0[2] = {t4[0], t4[2]}, b1[2] = {t4[1], t4[3]};
                mma16816(sc[nb * 2 + 0], qa + kt * 4, b0);
                mma16816(sc[nb * 2 + 1], qa + kt * 4, b1);
            }
        }
    }

    const float scale = 0.17677669529663687f;
    float m0 = -1e30f, m1 = -1e30f;
#pragma unroll
    for (int j = 0; j < 8; j++) {
#pragma unroll
        for (int i = 0; i < 4; i++) sc[j][i] *= scale;
        m0 = fmaxf(m0, fmaxf(sc[j][0], sc[j][1]));
        m1 = fmaxf(m1, fmaxf(sc[j][2], sc[j][3]));
    }
#pragma unroll
    for (int o = 1; o < 4; o <<= 1) {
        m0 = fmaxf(m0, __shfl_xor_sync(0xffffffffu, m0, o));
        m1 = fmaxf(m1, __shfl_xor_sync(0xffffffffu, m1, o));
    }
    float s0 = 0.f, s1 = 0.f;
#pragma unroll
    for (int j = 0; j < 8; j++) {
        sc[j][0] = __expf(sc[j][0] - m0);
        sc[j][1] = __expf(sc[j][1] - m0);
        sc[j][2] = __expf(sc[j][2] - m1);
        sc[j][3] = __expf(sc[j][3] - m1);
        s0 += sc[j][0] + sc[j][1];
        s1 += sc[j][2] + sc[j][3];
    }
#pragma unroll
    for (int o = 1; o < 4; o <<= 1) {
        s0 += __shfl_xor_sync(0xffffffffu, s0, o);
        s1 += __shfl_xor_sync(0xffffffffu, s1, o);
    }

    uint32_t phi[16], plo[16];
#pragma unroll
    for (int kt = 0; kt < 4; kt++) {
#pragma unroll
        for (int pos = 0; pos < 4; pos++) {
            int j = 2 * kt + (pos >> 1);
            float a = sc[j][(pos & 1) * 2 + 0];
            float b = sc[j][(pos & 1) * 2 + 1];
            __nv_bfloat16 h0 = __float2bfloat16(a), h1 = __float2bfloat16(b);
            phi[kt * 4 + pos] = packbf(h0, h1);
            plo[kt * 4 + pos] = packbf(__float2bfloat16(a - __bfloat162float(h0)),
                                       __float2bfloat16(b - __bfloat162float(h1)));
        }
    }

    float oc[4][4];
#pragma unroll
    for (int nb = 0; nb < 4; nb++)
#pragma unroll
        for (int i = 0; i < 4; i++) oc[nb][i] = 0.f;

#pragma unroll
    for (int pass = 0; pass < 3; pass++) {
        uint32_t vbase = (pass == 1) ? aVlo : aVhi;
        const uint32_t* pa = (pass == 2) ? plo : phi;
#pragma unroll
        for (int kt = 0; kt < 4; kt++) {
#pragma unroll
            for (int dh = 0; dh < 2; dh++) {
                uint32_t t4[4];
                ldm_x4_t(t4, vbase
                    + (kt * 16 + ((lane >> 3) & 1) * 8 + (lane & 7)) * (KVSTRIDE * 2)
                    + (dh * 16 + ((lane >> 4) & 1) * 8) * 2);
                uint32_t b0[2] = {t4[0], t4[1]}, b1[2] = {t4[2], t4[3]};
                mma16816(oc[dh * 2 + 0], pa + kt * 4, b0);
                mma16816(oc[dh * 2 + 1], pa + kt * 4, b1);
            }
        }
    }

    const float i0 = 1.f / s0, i1 = 1.f / s1;
#pragma unroll
    for (int nb = 0; nb < 4; nb++) {
#pragma unroll
        for (int half = 0; half < 2; half++) {
            int row = w * 64 + wq * 16 + g + half * 8;
            int col = h * 32 + nb * 8 + t2;
            float inv = half ? i1 : i0;
            float a = oc[nb][half * 2 + 0] * inv;
            float b = oc[nb][half * 2 + 1] * inv;
            *(uint32_t*)(g_xo + (size_t)row * 512 + col) = packh(a, b);
        }
    }
}

// ---------------------------------------------------------------------------
extern "C" void kernel_launch(void* const* d_in, const int* in_sizes, int n_in,
                              void* d_out, int out_size) {
    const float* x      = (const float*)d_in[0];
    const float* w_qkv  = (const float*)d_in[1];
    const float* w_proj = (const float*)d_in[2];
    const float* b_proj = (const float*)d_in[3];
    float* out = (float*)d_out;

    cudaFuncSetAttribute(gemm1_kernel, cudaFuncAttributeMaxDynamicSharedMemorySize, GSMEM4);

    gather_kernel<<<16384, 256>>>(x);
    wsplit_kernel<<<4096, 256>>>(w_qkv, w_proj);
    gemm1_kernel<<<dim3(512, 6), 256, GSMEM4>>>(nullptr, nullptr, 0);  // QKV
    attn_kernel<<<16384, 128>>>();                                     // HMMA attention
    gemm1_kernel<<<dim3(512, 2), 256, GSMEM4>>>(b_proj, out, 1);       // proj
}

// round 15
// speedup vs baseline: 2.3000x; 1.1281x over previous
#include <cuda_runtime.h>
#include <cuda_fp16.h>
#include <cstdint>

// Problem constants
#define NWIN   1024           // 16 batches * 8 * 8 windows
#define MTOT   65536          // NWIN * 64 tokens
#define CDIM   512
#define QKVN   1536

// Scratch (device globals — no allocation allowed)
__device__ __half        g_xw  [(size_t)MTOT * CDIM];        // A for QKV GEMM (fp16)
__device__ __half        g_qkv [(size_t)3 * MTOT * CDIM];    // fp16 [s][w][h][t][d]
__device__ __half        g_xo  [(size_t)MTOT * CDIM];        // A for proj GEMM (fp16)
__device__ __half        g_wq  [(size_t)QKVN * CDIM];        // fp16 weights
__device__ __half        g_wp  [(size_t)CDIM * CDIM];

// ---------------------------------------------------------------------------
// helpers (all plain sm_80-era PTX — valid on compute_103 base target)
// ---------------------------------------------------------------------------
__device__ __forceinline__ uint32_t smem_u32(const void* p) {
    uint32_t a;
    asm("{ .reg .u64 t; cvta.to.shared.u64 t, %1; cvt.u32.u64 %0, t; }" : "=r"(a) : "l"(p));
    return a;
}
__device__ __forceinline__ void cp16(uint32_t s, const void* g) {
    asm volatile("cp.async.cg.shared.global [%0], [%1], 16;" :: "r"(s), "l"(g));
}
__device__ __forceinline__ void ldm_x4(uint32_t* r, uint32_t addr) {
    asm volatile("ldmatrix.sync.aligned.m8n8.x4.shared.b16 {%0,%1,%2,%3}, [%4];"
                 : "=r"(r[0]), "=r"(r[1]), "=r"(r[2]), "=r"(r[3]) : "r"(addr));
}
__device__ __forceinline__ void ldm_x4_t(uint32_t* r, uint32_t addr) {
    asm volatile("ldmatrix.sync.aligned.m8n8.x4.trans.shared.b16 {%0,%1,%2,%3}, [%4];"
                 : "=r"(r[0]), "=r"(r[1]), "=r"(r[2]), "=r"(r[3]) : "r"(addr));
}
// fp16 mma
__device__ __forceinline__ void mma16816h(float* c, const uint32_t* a, const uint32_t* b) {
    asm volatile(
        "mma.sync.aligned.m16n8k16.row.col.f32.f16.f16.f32 "
        "{%0,%1,%2,%3}, {%4,%5,%6,%7}, {%8,%9}, {%0,%1,%2,%3};"
        : "+f"(c[0]), "+f"(c[1]), "+f"(c[2]), "+f"(c[3])
        : "r"(a[0]), "r"(a[1]), "r"(a[2]), "r"(a[3]), "r"(b[0]), "r"(b[1]));
}
__device__ __forceinline__ uint32_t packh(float a, float b) {
    __half ha = __float2half(a), hb = __float2half(b);
    uint32_t lo = *(uint16_t*)&ha, hi = *(uint16_t*)&hb;
    return lo | (hi << 16);
}

// ---------------------------------------------------------------------------
// 1) Gather + fp16 round: xw[w, t, cc] = fp16(x[b, n(i,j), c])
// ---------------------------------------------------------------------------
__global__ __launch_bounds__(256) void gather_kernel(const float* __restrict__ x) {
    int idx = blockIdx.x * blockDim.x + threadIdx.x;      // [0, NWIN*64*64)
    int cc64 = idx & 63;
    int t    = (idx >> 6) & 63;
    int w    = idx >> 12;
    int b  = w >> 6;
    int wh = (w >> 3) & 7;
    int ww = w & 7;
    int i = cc64 >> 3;
    int j = cc64 & 7;
    int base_c = (t & 7) * 64 + (t >> 3) * 8;
    int n = (wh * 8 + i) * 64 + (ww * 8 + j);
    const float* src = x + ((size_t)(b * 4096 + n)) * 512 + base_c;
    float4 v0 = *(const float4*)(src);
    float4 v1 = *(const float4*)(src + 4);
    float vv[8] = {v0.x, v0.y, v0.z, v0.w, v1.x, v1.y, v1.z, v1.w};
    size_t off = (size_t)w * 32768 + t * 512 + cc64;
#pragma unroll
    for (int r = 0; r < 8; r++) g_xw[off + 64 * r] = __float2half(vv[r]);
}

// ---------------------------------------------------------------------------
// 1b) Weight convert to fp16
// ---------------------------------------------------------------------------
__global__ __launch_bounds__(256) void wsplit_kernel(const float* __restrict__ wq,
                                                     const float* __restrict__ wp) {
    int i = blockIdx.x * blockDim.x + threadIdx.x;
    if (i < QKVN * CDIM) g_wq[i] = __float2half(wq[i]);
    else                 g_wp[i - QKVN * CDIM] = __float2half(wp[i - QKVN * CDIM]);
}

// ---------------------------------------------------------------------------
// 2) fp16 single-pass HMMA GEMM: D = A16 * B16 (fp32 accum).
//    CTA tile 128x256, warp tile 64x64, 8 warps, 2-stage cp.async pipeline,
//    K-chunk 64 (128B rows, XOR-16B swizzle, conflict-free ldmatrix).
//    mode 0: A=g_xw, B=g_wq, epilogue packs fp16 to g_qkv[s][w][h][t][d]
//    mode 1: A=g_xo, B=g_wp, epilogue bias + window-merge to out (fp32)
// ---------------------------------------------------------------------------
#define STG4   49152                 // A 16K | B 32K
#define GSMEM4 (2 * STG4 + 1024)
#define KCHUNKS 8

extern "C" __global__ __launch_bounds__(256, 1)
void gemm1_kernel(const float* __restrict__ bias, float* __restrict__ outp, int mode) {
    extern __shared__ char smem[];
    const int tid  = threadIdx.x;
    const int lane = tid & 31;
    const int wid  = tid >> 5;
    const int wm   = wid & 1;            // 2 warp rows (64 m each)
    const int wn   = wid >> 1;           // 4 warp cols (64 n each)
    const int m0 = blockIdx.x * 128;
    const int n0 = blockIdx.y * 256;

    const __half* A16 = (mode == 0) ? g_xw : g_xo;
    const __half* B16 = (mode == 0) ? g_wq : g_wp;

    uint32_t sbase = smem_u32(smem);
    uint32_t tile0 = (sbase + 1023) & ~1023u;

    float acc[4][8][4];
#pragma unroll
    for (int a = 0; a < 4; a++)
#pragma unroll
        for (int b = 0; b < 8; b++)
#pragma unroll
            for (int c = 0; c < 4; c++) acc[a][b][c] = 0.f;

    // ---- stage loader: one K-chunk (64) of A(128 rows), B(256 rows) ----
    auto load_stage = [&](int st, int kc) {
        int kb = kc << 6;
        uint32_t sg = tile0 + st * STG4;
#pragma unroll
        for (int v = 0; v < 4; v++) {                     // A: 1024 x 16B
            int c = tid + v * 256;
            int r = c >> 3, g = c & 7;
            uint32_t so = r * 128 + ((g ^ (r & 7)) << 4);
            cp16(sg + so, A16 + (size_t)(m0 + r) * 512 + kb + g * 8);
        }
#pragma unroll
        for (int v = 0; v < 8; v++) {                     // B: 2048 x 16B
            int c = tid + v * 256;
            int r = c >> 3, g = c & 7;
            uint32_t so = r * 128 + ((g ^ (r & 7)) << 4);
            cp16(sg + 16384 + so, B16 + (size_t)(n0 + r) * 512 + kb + g * 8);
        }
        asm volatile("cp.async.commit_group;" ::: "memory");
    };

    load_stage(0, 0);
    load_stage(1, 1);

    const int la = lane & 15;
    const int hi = lane >> 4;

    for (int it = 0; it < KCHUNKS; ++it) {
        asm volatile("cp.async.wait_group 1;" ::: "memory");
        __syncthreads();

        uint32_t sg = tile0 + (it & 1) * STG4;
#pragma unroll
        for (int s = 0; s < 4; s++) {                 // 4 x k16 in the chunk
            int ch = 2 * s + hi;
            uint32_t af[4][4];
#pragma unroll
            for (int mt = 0; mt < 4; mt++) {
                int r = wm * 64 + mt * 16 + la;
                ldm_x4(af[mt], sg + r * 128 + ((ch ^ (r & 7)) << 4));
            }
#pragma unroll
            for (int nh = 0; nh < 4; nh++) {          // 16 output cols each
                int r = wn * 64 + nh * 16 + la;
                uint32_t off = r * 128 + ((ch ^ (r & 7)) << 4);
                uint32_t th[4];
                ldm_x4(th, sg + 16384 + off);
                uint32_t bh0[2] = {th[0], th[2]}, bh1[2] = {th[1], th[3]};
#pragma unroll
                for (int mt = 0; mt < 4; mt++) {
                    mma16816h(acc[mt][nh * 2 + 0], af[mt], bh0);
                    mma16816h(acc[mt][nh * 2 + 1], af[mt], bh1);
                }
            }
        }
        __syncthreads();
        if (it + 2 < KCHUNKS) load_stage(it & 1, it + 2);
        else asm volatile("cp.async.commit_group;" ::: "memory");
    }

    // ---- epilogue straight from C fragments ----
    const int row0 = lane >> 2;
    const int col0 = (lane & 3) * 2;
#pragma unroll
    for (int mt = 0; mt < 4; mt++) {
#pragma unroll
        for (int half = 0; half < 2; half++) {
            int m = m0 + wm * 64 + mt * 16 + row0 + half * 8;
            int w = m >> 6, tt = m & 63;
#pragma unroll
            for (int nt = 0; nt < 8; nt++) {
                int n = n0 + wn * 64 + nt * 8 + col0;
                float v0 = acc[mt][nt][half * 2 + 0];
                float v1 = acc[mt][nt][half * 2 + 1];
                if (mode == 0) {
                    int s = n >> 9, h = (n >> 5) & 15, d = n & 31;
                    __half* dst = g_qkv + (((size_t)s * NWIN + w) * 16 + h) * 2048
                                + (size_t)tt * 32 + d;
                    *(uint32_t*)dst = packh(v0, v1);
                } else {
                    int b  = w >> 6;
                    int wh = (w >> 3) & 7;
                    int ww = w & 7;
                    int p = tt >> 3, q = tt & 7;
                    int npos = (wh * 8 + p) * 64 + (ww * 8 + q);
                    float2 bi = *(const float2*)(bias + n);
                    float* dst = outp + ((size_t)(b * 4096 + npos)) * 512 + n;
                    *(float2*)dst = make_float2(v0 + bi.x, v1 + bi.y);
                }
            }
        }
    }
}

// ---------------------------------------------------------------------------
// 3) Attention v4 (fp16 single-pass HMMA): one CTA per (window, head),
//    4 warps x 16 query rows. Q/K/V already fp16 in g_qkv. S and O each take
//    ONE mma pass. Softmax fp32 in registers with shfl row reductions.
// ---------------------------------------------------------------------------
#define KVSTRIDE 40   // fp16 elems per row (80B) -> conflict-free ldmatrix

__global__ __launch_bounds__(128) void attn_kernel() {
    __shared__ __half Ks[64 * KVSTRIDE];
    __shared__ __half Vs[64 * KVSTRIDE];
    const int tid = threadIdx.x;
    const int w = blockIdx.x >> 4;
    const int h = blockIdx.x & 15;
    const size_t base = ((size_t)w * 16 + h) * 2048;
    const __half* qb = g_qkv + base;
    const __half* kb = g_qkv + (size_t)MTOT * 512 + base;
    const __half* vb = g_qkv + (size_t)2 * MTOT * 512 + base;

    // ---- stage K,V: 64 rows x 32 halfs = 256 uint4 each; 2 per thread ----
#pragma unroll
    for (int v = 0; v < 2; v++) {
        int ui = tid + v * 128;                 // [0,256): uint4 index
        int row = ui >> 2, d0 = (ui & 3) * 8;
        *(uint4*)(Ks + row * KVSTRIDE + d0) = *(const uint4*)(kb + row * 32 + d0);
        *(uint4*)(Vs + row * KVSTRIDE + d0) = *(const uint4*)(vb + row * 32 + d0);
    }
    __syncthreads();

    const int lane = tid & 31, wq = tid >> 5;
    const int g  = lane >> 2;            // row within 8
    const int t2 = (lane & 3) * 2;       // col pair
    const uint32_t aK = smem_u32(Ks);
    const uint32_t aV = smem_u32(Vs);

    // ---- Q fragments straight from gmem (fp16 pairs) ----
    uint32_t qf[8];
#pragma unroll
    for (int kt = 0; kt < 2; kt++)
#pragma unroll
        for (int pos = 0; pos < 4; pos++) {
            int row = wq * 16 + g + (pos & 1) * 8;
            int col = kt * 16 + t2 + (pos >> 1) * 8;
            qf[kt * 4 + pos] = *(const uint32_t*)(qb + row * 32 + col);
        }

    // ---- S = Q K^T : single fp16 pass ----
    float sc[8][4];
#pragma unroll
    for (int j = 0; j < 8; j++)
#pragma unroll
        for (int i = 0; i < 4; i++) sc[j][i] = 0.f;

#pragma unroll
    for (int kt = 0; kt < 2; kt++) {
#pragma unroll
        for (int nb = 0; nb < 4; nb++) {
            uint32_t t4[4];
            ldm_x4(t4, aK + (nb * 16 + (lane & 15)) * (KVSTRIDE * 2)
                         + (kt * 2 + (lane >> 4)) * 16);
            uint32_t b0[2] = {t4[0], t4[2]}, b1[2] = {t4[1], t4[3]};
            mma16816h(sc[nb * 2 + 0], qf + kt * 4, b0);
            mma16816h(sc[nb * 2 + 1], qf + kt * 4, b1);
        }
    }

    // ---- softmax (rows g and g+8; reduce over 4 lanes sharing g) ----
    const float scale = 0.17677669529663687f;
    float m0 = -1e30f, m1 = -1e30f;
#pragma unroll
    for (int j = 0; j < 8; j++) {
#pragma unroll
        for (int i = 0; i < 4; i++) sc[j][i] *= scale;
        m0 = fmaxf(m0, fmaxf(sc[j][0], sc[j][1]));
        m1 = fmaxf(m1, fmaxf(sc[j][2], sc[j][3]));
    }
#pragma unroll
    for (int o = 1; o < 4; o <<= 1) {
        m0 = fmaxf(m0, __shfl_xor_sync(0xffffffffu, m0, o));
        m1 = fmaxf(m1, __shfl_xor_sync(0xffffffffu, m1, o));
    }
    float s0 = 0.f, s1 = 0.f;
#pragma unroll
    for (int j = 0; j < 8; j++) {
        sc[j][0] = __expf(sc[j][0] - m0);
        sc[j][1] = __expf(sc[j][1] - m0);
        sc[j][2] = __expf(sc[j][2] - m1);
        sc[j][3] = __expf(sc[j][3] - m1);
        s0 += sc[j][0] + sc[j][1];
        s1 += sc[j][2] + sc[j][3];
    }
#pragma unroll
    for (int o = 1; o < 4; o <<= 1) {
        s0 += __shfl_xor_sync(0xffffffffu, s0, o);
        s1 += __shfl_xor_sync(0xffffffffu, s1, o);
    }

    // ---- P fragments (fp16, in-register C->A permute) ----
    uint32_t pf[16];
#pragma unroll
    for (int kt = 0; kt < 4; kt++) {
#pragma unroll
        for (int pos = 0; pos < 4; pos++) {
            int j = 2 * kt + (pos >> 1);
            pf[kt * 4 + pos] = packh(sc[j][(pos & 1) * 2 + 0],
                                     sc[j][(pos & 1) * 2 + 1]);
        }
    }

    // ---- O = P V : single fp16 pass, V via ldmatrix.trans ----
    float oc[4][4];
#pragma unroll
    for (int nb = 0; nb < 4; nb++)
#pragma unroll
        for (int i = 0; i < 4; i++) oc[nb][i] = 0.f;

#pragma unroll
    for (int kt = 0; kt < 4; kt++) {
#pragma unroll
        for (int dh = 0; dh < 2; dh++) {
            uint32_t t4[4];
            ldm_x4_t(t4, aV
                + (kt * 16 + ((lane >> 3) & 1) * 8 + (lane & 7)) * (KVSTRIDE * 2)
                + (dh * 16 + ((lane >> 4) & 1) * 8) * 2);
            uint32_t b0[2] = {t4[0], t4[1]}, b1[2] = {t4[2], t4[3]};
            mma16816h(oc[dh * 2 + 0], pf + kt * 4, b0);
            mma16816h(oc[dh * 2 + 1], pf + kt * 4, b1);
        }
    }

    // ---- normalize + emit fp16 xo for proj GEMM ----
    const float i0 = 1.f / s0, i1 = 1.f / s1;
#pragma unroll
    for (int nb = 0; nb < 4; nb++) {
#pragma unroll
        for (int half = 0; half < 2; half++) {
            int row = w * 64 + wq * 16 + g + half * 8;
            int col = h * 32 + nb * 8 + t2;
            float inv = half ? i1 : i0;
            *(uint32_t*)(g_xo + (size_t)row * 512 + col) =
                packh(oc[nb][half * 2 + 0] * inv, oc[nb][half * 2 + 1] * inv);
        }
    }
}

// ---------------------------------------------------------------------------
extern "C" void kernel_launch(void* const* d_in, const int* in_sizes, int n_in,
                              void* d_out, int out_size) {
    const float* x      = (const float*)d_in[0];
    const float* w_qkv  = (const float*)d_in[1];
    const float* w_proj = (const float*)d_in[2];
    const float* b_proj = (const float*)d_in[3];
    float* out = (float*)d_out;

    cudaFuncSetAttribute(gemm1_kernel, cudaFuncAttributeMaxDynamicSharedMemorySize, GSMEM4);

    gather_kernel<<<16384, 256>>>(x);
    wsplit_kernel<<<4096, 256>>>(w_qkv, w_proj);
    gemm1_kernel<<<dim3(512, 6), 256, GSMEM4>>>(nullptr, nullptr, 0);  // QKV
    attn_kernel<<<16384, 128>>>();                                     // fp16 attention
    gemm1_kernel<<<dim3(512, 2), 256, GSMEM4>>>(b_proj, out, 1);       // proj
}